// round 1
// baseline (speedup 1.0000x reference)
#include <cuda_runtime.h>
#include <math.h>

#define HH 24
#define WW 24
#define NPIX 576
#define DD 1024
#define BB 32
#define KS 256
#define MT 128
#define NT 577

// ---------------- scratch (device globals; no allocation allowed) ----------
__device__ float g_dw[(size_t)BB * NPIX * DD];      // depthwise conv output (75.5 MB)
__device__ int   g_parent[BB * NPIX];               // argmax parents / roots
__device__ float g_cntf[BB * KS];                   // per-slot counts (float)
__device__ int   g_start[BB * KS];                  // member-list offsets
__device__ int   g_mem[BB * NPIX];                  // member lists (grouped by slot)
__device__ float g_C[(size_t)BB * KS * DD];         // cluster centers (33.5 MB)
__device__ float g_Qc[BB * DD];                     // Q_cls
__device__ float g_upart[4 * BB * DD];              // partial u (per d-chunk)
__device__ float g_u[BB * DD];                      // u = Q_cls @ v_w
__device__ float g_spart[BB * KS * 4];              // partial scores (per d-quarter)
__device__ int   g_sel[BB * MT];                    // final top-128 slot ids

// ---------------- Kernel 1: depthwise 3x3 conv (zero pad, cross-corr) ------
// grid (6 hgroups, B, 4 d-chunk-groups), 256 threads. Shared 6 rows x 26 w x 64 d.
__global__ void k_dwconv(const float* __restrict__ tok2d,
                         const float* __restrict__ dww) {
    __shared__ float s_rows[6 * 26 * 64];
    const int t    = threadIdx.x;
    const int h0   = blockIdx.x * 4;
    const int b    = blockIdx.y;
    const int dloc = t & 63;
    const int wg   = t >> 6;

    for (int c = blockIdx.z * 4; c < blockIdx.z * 4 + 4; c++) {
        const int dbase = c * 64;
        for (int l = t; l < 6 * 26 * 64; l += 256) {
            int rr  = l / (26 * 64);
            int rem = l - rr * (26 * 64);
            int wc  = rem >> 6;
            int d   = rem & 63;
            int gh  = h0 + rr - 1;
            int gw  = wc - 1;
            float v = 0.f;
            if (gh >= 0 && gh < HH && gw >= 0 && gw < WW)
                v = tok2d[((size_t)b * NT + 1 + gh * WW + gw) * DD + dbase + d];
            s_rows[l] = v;
        }
        __syncthreads();
        const int dglob = dbase + dloc;
        float wr[9];
#pragma unroll
        for (int k = 0; k < 9; k++) wr[k] = dww[dglob * 9 + k];
#pragma unroll
        for (int r = 0; r < 4; r++) {
            for (int w = wg; w < WW; w += 4) {
                float s = 0.f;
#pragma unroll
                for (int kh = 0; kh < 3; kh++)
#pragma unroll
                    for (int kw = 0; kw < 3; kw++)
                        s += s_rows[((r + kh) * 26 + (w + kw)) * 64 + dloc] * wr[kh * 3 + kw];
                g_dw[((size_t)b * NPIX + (h0 + r) * WW + w) * DD + dglob] = s;
            }
        }
        __syncthreads();
    }
}

// ---------------- Kernel 2: pointwise 1x1 (D->9) + softmax + row argmax ----
// warp per pixel; grid B*N/8 blocks of 256.
__global__ void k_affinity(const float* __restrict__ pww,
                           const float* __restrict__ pwb) {
    __shared__ float s_pw[9 * DD];
    const int t = threadIdx.x;
    for (int l = t; l < 9 * DD; l += 256) s_pw[l] = pww[l];
    __syncthreads();
    const int warp = t >> 5, lane = t & 31;
    const int pix = blockIdx.x * 8 + warp;
    const int b = pix / NPIX, n = pix - b * NPIX;

    float acc[9];
#pragma unroll
    for (int o = 0; o < 9; o++) acc[o] = 0.f;
    const float* row = g_dw + (size_t)(b * NPIX + n) * DD;
    for (int i = 0; i < 32; i++) {
        int d = lane + 32 * i;
        float x = row[d];
#pragma unroll
        for (int o = 0; o < 9; o++) acc[o] += x * s_pw[o * DD + d];
    }
#pragma unroll
    for (int o = 0; o < 9; o++)
        for (int off = 16; off; off >>= 1)
            acc[o] += __shfl_xor_sync(0xffffffffu, acc[o], off);

    if (lane == 0) {
        float l9[9], mx = -1e30f;
#pragma unroll
        for (int o = 0; o < 9; o++) { l9[o] = acc[o] + pwb[o]; mx = fmaxf(mx, l9[o]); }
        float e[9];
#pragma unroll
        for (int o = 0; o < 9; o++) e[o] = expf(l9[o] - mx);
        // argmax over per-row sums of exp (common softmax denominator -> same argmax)
        const int h = n / WW, w = n - (n / WW) * WW;
        float cs[9]; int cid[9]; int m = 0;
        for (int k = 0; k < 9; k++) {
            int dy = k / 3 - 1, dx = k % 3 - 1;
            int ny = min(max(h + dy, 0), HH - 1);
            int nx = min(max(w + dx, 0), WW - 1);
            int col = ny * WW + nx;
            int found = -1;
            for (int j = 0; j < m; j++) if (cid[j] == col) { found = j; break; }
            if (found >= 0) cs[found] += e[k];
            else { cid[m] = col; cs[m] = e[k]; m++; }
        }
        int best = cid[0]; float bs = cs[0];
        for (int j = 1; j < m; j++)
            if (cs[j] > bs || (cs[j] == bs && cid[j] < best)) { bs = cs[j]; best = cid[j]; }
        g_parent[b * NPIX + n] = best;
    }
}

// ---------------- Kernel 3: pointer jumping + top-256 clusters + members ---
// one block per batch, 576 threads. Fully deterministic (no float atomics,
// member positions = rank-by-index).
__global__ void k_cluster() {
    __shared__ int s_par[NPIX], s_cnt[NPIX], s_hist[NPIX + 1];
    __shared__ int s_flag[NPIX], s_slotof[NPIX], s_startsh[KS];
    __shared__ int s_cstar, s_take;
    const int i = threadIdx.x;
    const int b = blockIdx.x;

    s_par[i] = g_parent[b * NPIX + i];
    __syncthreads();
    for (int it = 0; it < 6; it++) {            // roots = roots[roots], x6
        int v = s_par[s_par[i]];
        __syncthreads();
        s_par[i] = v;
        __syncthreads();
    }
    s_cnt[i] = 0; s_hist[i] = 0;
    if (i == 0) s_hist[NPIX] = 0;
    __syncthreads();
    atomicAdd(&s_cnt[s_par[i]], 1);
    __syncthreads();
    atomicAdd(&s_hist[s_cnt[i]], 1);
    __syncthreads();
    // threshold count c*: select all cnt>c*, plus first (256-#gt) with cnt==c*
    {
        int nrep = (i == 0) ? 2 : 1;
        for (int rep = 0; rep < nrep; rep++) {
            int v = (rep == 0) ? i : NPIX;
            int gt = 0;
            for (int vv = v + 1; vv <= NPIX; vv++) gt += s_hist[vv];
            if (gt < KS && gt + s_hist[v] >= KS) { s_cstar = v; s_take = KS - gt; }
        }
    }
    __syncthreads();
    const int cstar = s_cstar, take = s_take;
    const int ci = s_cnt[i];
    int eqb = 0;
    for (int j = 0; j < i; j++) eqb += (s_cnt[j] == cstar);
    const int fl = (ci > cstar) || (ci == cstar && eqb < take);
    s_flag[i] = fl;
    __syncthreads();
    int slot = 0, start = 0;
    for (int j = 0; j < i; j++) {
        int f = s_flag[j];
        slot += f;
        start += f ? s_cnt[j] : 0;
    }
    s_slotof[i] = fl ? slot : -1;
    if (fl) {
        g_cntf[b * KS + slot]  = (float)ci;
        g_start[b * KS + slot] = start;
        s_startsh[slot] = start;
    }
    __syncthreads();
    const int r = s_par[i];
    const int sl = s_slotof[r];
    if (sl >= 0) {
        int pos = 0;
        for (int j = 0; j < i; j++) pos += (s_slotof[s_par[j]] == sl);
        g_mem[b * NPIX + s_startsh[sl] + pos] = i;
    }
}

// ---------------- Kernel 4: Q_cls = cls @ q_w.T + q_b ----------------------
// grid 128 blocks x 256 threads; warp per output d, all 32 batches in regs.
__global__ void k_qcls(const float* __restrict__ tok2d,
                       const float* __restrict__ qw,
                       const float* __restrict__ qb) {
    __shared__ float s_cls[32 * 256];
    const int t = threadIdx.x, lane = t & 31, warp = t >> 5;
    const int d = blockIdx.x * 8 + warp;
    float acc[32];
#pragma unroll
    for (int b = 0; b < 32; b++) acc[b] = 0.f;
    for (int ec = 0; ec < 4; ec++) {
        __syncthreads();
        for (int l = t; l < 32 * 256; l += 256) {
            int b = l >> 8, e = l & 255;
            s_cls[l] = tok2d[(size_t)b * NT * DD + ec * 256 + e];
        }
        __syncthreads();
        for (int ii = 0; ii < 8; ii++) {
            int el = lane + 32 * ii;
            float wv = qw[(size_t)d * DD + ec * 256 + el];
#pragma unroll
            for (int b = 0; b < 32; b++) acc[b] += wv * s_cls[b * 256 + el];
        }
    }
    const float qbd = qb[d];
    for (int b = 0; b < 32; b++) {
        float v = acc[b];
        for (int off = 16; off; off >>= 1) v += __shfl_xor_sync(0xffffffffu, v, off);
        if (lane == 0) g_Qc[b * DD + d] = v + qbd;
    }
}

// ---------------- Kernel 5: u_part = Qc @ v_w (d-chunked partials) ---------
// grid (8 e-tiles, 4 d-chunks), 128 threads; deterministic partials.
__global__ void k_u(const float* __restrict__ vw) {
    __shared__ float s_qc[256 * 32];  // [d][b]
    const int t = threadIdx.x;
    const int e = blockIdx.x * 128 + t;
    const int dc0 = blockIdx.y * 256;
    for (int l = t; l < 256 * 32; l += 128) {
        int d = l >> 5, b = l & 31;
        s_qc[l] = g_Qc[b * DD + dc0 + d];
    }
    __syncthreads();
    float acc[32];
#pragma unroll
    for (int b = 0; b < 32; b++) acc[b] = 0.f;
    for (int dd = 0; dd < 256; dd++) {
        float v = vw[(size_t)(dc0 + dd) * DD + e];
        const float4* q4 = (const float4*)&s_qc[dd * 32];
#pragma unroll
        for (int j = 0; j < 8; j++) {
            float4 q = q4[j];
            acc[4 * j + 0] += q.x * v;
            acc[4 * j + 1] += q.y * v;
            acc[4 * j + 2] += q.z * v;
            acc[4 * j + 3] += q.w * v;
        }
    }
#pragma unroll
    for (int b = 0; b < 32; b++)
        g_upart[blockIdx.y * (BB * DD) + b * DD + e] = acc[b];
}

__global__ void k_sumu() {
    int idx = blockIdx.x * 256 + threadIdx.x;
    float s = 0.f;
#pragma unroll
    for (int z = 0; z < 4; z++) s += g_upart[z * (BB * DD) + idx];
    g_u[idx] = s;
}

// ---------------- Kernel 6: centers C + partial scores ---------------------
// grid (256 slots, B, 4 d-quarters), 256 threads (one d each).
__global__ void k_centers(const float* __restrict__ tok2d) {
    const int s = blockIdx.x, b = blockIdx.y, z = blockIdx.z;
    const int t = threadIdx.x;
    const int d = z * 256 + t;
    const int start = g_start[b * KS + s];
    const float cf = g_cntf[b * KS + s];
    const int cnt = (int)cf;
    float acc = 0.f;
    const int* mem = g_mem + b * NPIX + start;
    for (int m = 0; m < cnt; m++) {
        int i = mem[m];
        acc += tok2d[((size_t)b * NT + 1 + i) * DD + d];
    }
    const float c = acc / fmaxf(cf, 1.f);
    g_C[((size_t)b * KS + s) * DD + d] = c;
    float part = c * g_u[b * DD + d];
    __shared__ float red[8];
    for (int off = 16; off; off >>= 1) part += __shfl_xor_sync(0xffffffffu, part, off);
    if ((t & 31) == 0) red[t >> 5] = part;
    __syncthreads();
    if (t < 8) {
        float v = red[t];
        for (int off = 4; off; off >>= 1) v += __shfl_xor_sync(0xffu, v, off);
        if (t == 0) g_spart[(b * KS + s) * 4 + z] = v;
    }
}

// ---------------- Kernel 7: top-128 of scores (ties -> lower index) --------
__global__ void k_top() {
    __shared__ float ss[KS];
    __shared__ int fl[KS];
    const int t = threadIdx.x, b = blockIdx.x;
    const float cf = g_cntf[b * KS + t];
    float sc = 0.f;
#pragma unroll
    for (int z = 0; z < 4; z++) sc += g_spart[(b * KS + t) * 4 + z];
    ss[t] = (cf > 0.f) ? sc : -INFINITY;
    __syncthreads();
    const float sv = ss[t];
    int rank = 0;
    for (int k = 0; k < KS; k++) {
        float o = ss[k];
        rank += (o > sv) || (o == sv && k < t);
    }
    fl[t] = (rank < MT);
    __syncthreads();
    if (fl[t]) {
        int pos = 0;
        for (int k = 0; k < t; k++) pos += fl[k];
        g_sel[b * MT + pos] = t;
    }
}

// ---------------- Kernel 8: gather output ----------------------------------
__global__ void k_gather(float* __restrict__ out) {
    const int tt = blockIdx.x, b = blockIdx.y, t = threadIdx.x;
    const int k = g_sel[b * MT + tt];
    const float4* src = (const float4*)(g_C + ((size_t)b * KS + k) * DD);
    float4* dst = (float4*)(out + ((size_t)b * MT + tt) * DD);
    dst[t] = src[t];
}

// ---------------------------------------------------------------------------
extern "C" void kernel_launch(void* const* d_in, const int* in_sizes, int n_in,
                              void* d_out, int out_size) {
    (void)in_sizes; (void)n_in; (void)out_size;
    const float* tok2d = (const float*)d_in[0];
    const float* dw_w  = (const float*)d_in[1];
    const float* pw_w  = (const float*)d_in[2];
    const float* pw_b  = (const float*)d_in[3];
    const float* q_w   = (const float*)d_in[4];
    const float* q_b   = (const float*)d_in[5];
    const float* v_w   = (const float*)d_in[6];
    float* out = (float*)d_out;

    k_dwconv  <<<dim3(6, BB, 4), 256>>>(tok2d, dw_w);
    k_affinity<<<BB * NPIX / 8, 256>>>(pw_w, pw_b);
    k_cluster <<<BB, NPIX>>>();
    k_qcls    <<<128, 256>>>(tok2d, q_w, q_b);
    k_u       <<<dim3(8, 4), 128>>>(v_w);
    k_sumu    <<<BB * DD / 256, 256>>>();
    k_centers <<<dim3(KS, BB, 4), 256>>>(tok2d);
    k_top     <<<BB, 256>>>();
    k_gather  <<<dim3(MT, BB), 256>>>(out);
}

// round 2
// speedup vs baseline: 1.1189x; 1.1189x over previous
#include <cuda_runtime.h>
#include <math.h>

#define HH 24
#define WW 24
#define NPIX 576
#define DD 1024
#define BB 32
#define KS 256
#define MT 128
#define NT 577

// ---------------- scratch (device globals; no allocation allowed) ----------
__device__ float g_affp[4][BB * NPIX * 9];          // partial 9-logits per d-quarter
__device__ int   g_parent[BB * NPIX];               // argmax parents / roots
__device__ float g_cntf[BB * KS];                   // per-slot counts (float)
__device__ int   g_start[BB * KS];                  // member-list offsets
__device__ int   g_mem[BB * NPIX];                  // member lists (grouped by slot)
__device__ float g_C[(size_t)BB * KS * DD];         // cluster centers (33.5 MB)
__device__ float g_qpart[4][BB * DD];               // partial Q_cls (per e-chunk)
__device__ float g_upart[16][BB * DD];              // partial u (per d-chunk)
__device__ float g_u[BB * DD];                      // u = Q_cls @ v_w
__device__ float g_spart[BB * KS * 4];              // partial scores (per d-quarter)
__device__ int   g_sel[BB * MT];                    // final top-128 slot ids

// ---------------- Kernel 1: FUSED depthwise 3x3 + pointwise (D->9) --------
// grid (6 hgroups of 4 rows, B, 4 d-quarters), 384 threads.
// thread = (quad of 4 w-pixels, j of 16 d-lanes); warp = 2 quads x 16 j.
// Partial 9-logit sums per quarter -> g_affp. Fully deterministic.
__global__ void k_affdw(const float* __restrict__ tok2d,
                        const float* __restrict__ dww,
                        const float* __restrict__ pww) {
    __shared__ float s_tile[32 * 157];   // [d-lane][row*26+col], pad 157
    __shared__ float s_dww[256 * 9];     // [dq][k]
    __shared__ float s_pw[9 * 256];      // [o][dq]
    const int t  = threadIdx.x;
    const int h0 = blockIdx.x * 4;
    const int b  = blockIdx.y;
    const int z  = blockIdx.z;

    for (int l = t; l < 256 * 9; l += 384) s_dww[l] = dww[z * 256 * 9 + l];
    for (int l = t; l < 9 * 256; l += 384) {
        int o = l >> 8, dq = l & 255;
        s_pw[l] = pww[o * DD + z * 256 + dq];
    }

    const int quad = t >> 4;          // 0..23
    const int j    = t & 15;          // d-lane
    const int qr   = quad / 6;        // pixel row within group (0..3)
    const int qw   = (quad % 6) * 4;  // base pixel col

    float acc[36];
#pragma unroll
    for (int i = 0; i < 36; i++) acc[i] = 0.f;

    for (int ch = 0; ch < 8; ch++) {
        __syncthreads();
        for (int l = t; l < 32 * 156; l += 384) {
            int dl = l & 31, pos = l >> 5;
            int c = pos % 26, r = pos / 26;
            int gh = h0 + r - 1, gw = c - 1;
            float v = 0.f;
            if (gh >= 0 && gh < HH && gw >= 0 && gw < WW)
                v = tok2d[((size_t)(b * NT + 1 + gh * WW + gw)) * DD + z * 256 + ch * 32 + dl];
            s_tile[dl * 157 + pos] = v;
        }
        __syncthreads();
#pragma unroll
        for (int i = 0; i < 2; i++) {
            const int dl = i * 16 + j;
            const int dq = ch * 32 + dl;
            float wd[9], wp[9];
#pragma unroll
            for (int k = 0; k < 9; k++) wd[k] = s_dww[dq * 9 + k];
#pragma unroll
            for (int o = 0; o < 9; o++) wp[o] = s_pw[o * 256 + dq];
            float tv[3][6];
#pragma unroll
            for (int kh = 0; kh < 3; kh++)
#pragma unroll
                for (int c6 = 0; c6 < 6; c6++)
                    tv[kh][c6] = s_tile[dl * 157 + (qr + kh) * 26 + qw + c6];
#pragma unroll
            for (int px = 0; px < 4; px++) {
                float dwv = 0.f;
#pragma unroll
                for (int kh = 0; kh < 3; kh++)
#pragma unroll
                    for (int kw = 0; kw < 3; kw++)
                        dwv += tv[kh][px + kw] * wd[kh * 3 + kw];
#pragma unroll
                for (int o = 0; o < 9; o++) acc[px * 9 + o] += dwv * wp[o];
            }
        }
    }
    // reduce over the 16 d-lanes (within half-warp; deterministic shuffle tree)
#pragma unroll
    for (int i = 0; i < 36; i++)
#pragma unroll
        for (int off = 8; off; off >>= 1)
            acc[i] += __shfl_xor_sync(0xffffffffu, acc[i], off);

    if (j == 0) {
#pragma unroll
        for (int px = 0; px < 4; px++) {
            int n = (h0 + qr) * WW + qw + px;
            float* dst = &g_affp[z][(b * NPIX + n) * 9];
#pragma unroll
            for (int o = 0; o < 9; o++) dst[o] = acc[px * 9 + o];
        }
    }
}

// ---------------- Kernel 1b: combine quarters, softmax + dedup argmax ------
__global__ void k_parent(const float* __restrict__ pwb) {
    const int pix = blockIdx.x * 128 + threadIdx.x;
    const int b = pix / NPIX, n = pix - b * NPIX;
    float l9[9];
#pragma unroll
    for (int o = 0; o < 9; o++) l9[o] = pwb[o];
#pragma unroll
    for (int z = 0; z < 4; z++) {
        const float* src = &g_affp[z][(b * NPIX + n) * 9];
#pragma unroll
        for (int o = 0; o < 9; o++) l9[o] += src[o];
    }
    float mx = -1e30f;
#pragma unroll
    for (int o = 0; o < 9; o++) mx = fmaxf(mx, l9[o]);
    float e[9];
#pragma unroll
    for (int o = 0; o < 9; o++) e[o] = expf(l9[o] - mx);
    const int h = n / WW, w = n - (n / WW) * WW;
    float cs[9]; int cid[9]; int m = 0;
    for (int k = 0; k < 9; k++) {
        int dy = k / 3 - 1, dx = k % 3 - 1;
        int ny = min(max(h + dy, 0), HH - 1);
        int nx = min(max(w + dx, 0), WW - 1);
        int col = ny * WW + nx;
        int found = -1;
        for (int jj = 0; jj < m; jj++) if (cid[jj] == col) { found = jj; break; }
        if (found >= 0) cs[found] += e[k];
        else { cid[m] = col; cs[m] = e[k]; m++; }
    }
    int best = cid[0]; float bs = cs[0];
    for (int jj = 1; jj < m; jj++)
        if (cs[jj] > bs || (cs[jj] == bs && cid[jj] < best)) { bs = cs[jj]; best = cid[jj]; }
    g_parent[b * NPIX + n] = best;
}

// ---------------- Kernel 3: pointer jumping + top-256 clusters + members ---
__global__ void k_cluster() {
    __shared__ int s_par[NPIX], s_cnt[NPIX], s_hist[NPIX + 1];
    __shared__ int s_flag[NPIX], s_slotof[NPIX], s_startsh[KS];
    __shared__ int s_cstar, s_take;
    const int i = threadIdx.x;
    const int b = blockIdx.x;

    s_par[i] = g_parent[b * NPIX + i];
    __syncthreads();
    for (int it = 0; it < 6; it++) {
        int v = s_par[s_par[i]];
        __syncthreads();
        s_par[i] = v;
        __syncthreads();
    }
    s_cnt[i] = 0; s_hist[i] = 0;
    if (i == 0) s_hist[NPIX] = 0;
    __syncthreads();
    atomicAdd(&s_cnt[s_par[i]], 1);
    __syncthreads();
    atomicAdd(&s_hist[s_cnt[i]], 1);
    __syncthreads();
    {
        int nrep = (i == 0) ? 2 : 1;
        for (int rep = 0; rep < nrep; rep++) {
            int v = (rep == 0) ? i : NPIX;
            int gt = 0;
            for (int vv = v + 1; vv <= NPIX; vv++) gt += s_hist[vv];
            if (gt < KS && gt + s_hist[v] >= KS) { s_cstar = v; s_take = KS - gt; }
        }
    }
    __syncthreads();
    const int cstar = s_cstar, take = s_take;
    const int ci = s_cnt[i];
    int eqb = 0;
    for (int j = 0; j < i; j++) eqb += (s_cnt[j] == cstar);
    const int fl = (ci > cstar) || (ci == cstar && eqb < take);
    s_flag[i] = fl;
    __syncthreads();
    int slot = 0, start = 0;
    for (int j = 0; j < i; j++) {
        int f = s_flag[j];
        slot += f;
        start += f ? s_cnt[j] : 0;
    }
    s_slotof[i] = fl ? slot : -1;
    if (fl) {
        g_cntf[b * KS + slot]  = (float)ci;
        g_start[b * KS + slot] = start;
        s_startsh[slot] = start;
    }
    __syncthreads();
    const int r = s_par[i];
    const int sl = s_slotof[r];
    if (sl >= 0) {
        int pos = 0;
        for (int j = 0; j < i; j++) pos += (s_slotof[s_par[j]] == sl);
        g_mem[b * NPIX + s_startsh[sl] + pos] = i;
    }
}

// ---------------- Kernel 4: Q_cls partials (cls @ q_w.T), e-chunked --------
// grid (128 d-groups, 4 e-chunks) x 256 threads; warp per output d.
__global__ void k_qcls(const float* __restrict__ tok2d,
                       const float* __restrict__ qw) {
    __shared__ float s_cls[32 * 256];
    const int t = threadIdx.x, lane = t & 31, warp = t >> 5;
    const int d = blockIdx.x * 8 + warp;
    const int ec = blockIdx.y;
    for (int l = t; l < 32 * 256; l += 256) {
        int b = l >> 8, e = l & 255;
        s_cls[l] = tok2d[(size_t)b * NT * DD + ec * 256 + e];
    }
    __syncthreads();
    float acc[32];
#pragma unroll
    for (int b = 0; b < 32; b++) acc[b] = 0.f;
#pragma unroll
    for (int ii = 0; ii < 8; ii++) {
        int el = lane + 32 * ii;
        float wv = qw[(size_t)d * DD + ec * 256 + el];
#pragma unroll
        for (int b = 0; b < 32; b++) acc[b] += wv * s_cls[b * 256 + el];
    }
    for (int b = 0; b < 32; b++) {
        float v = acc[b];
        for (int off = 16; off; off >>= 1) v += __shfl_xor_sync(0xffffffffu, v, off);
        if (lane == 0) g_qpart[ec][b * DD + d] = v;
    }
}

// ---------------- Kernel 5: u partials = Qc @ v_w, d-chunked ---------------
// grid (8 e-tiles of 128, 16 d-chunks of 64), 128 threads.
__global__ void k_u(const float* __restrict__ vw,
                    const float* __restrict__ qb) {
    __shared__ float s_qc[64 * 32];  // [d][b]
    const int t = threadIdx.x;
    const int e = blockIdx.x * 128 + t;
    const int dc0 = blockIdx.y * 64;
    for (int l = t; l < 64 * 32; l += 128) {
        int d = l >> 5, b = l & 31;
        float v = qb[dc0 + d];
#pragma unroll
        for (int z = 0; z < 4; z++) v += g_qpart[z][b * DD + dc0 + d];
        s_qc[l] = v;
    }
    __syncthreads();
    float acc[32];
#pragma unroll
    for (int b = 0; b < 32; b++) acc[b] = 0.f;
    for (int dd = 0; dd < 64; dd++) {
        float v = vw[(size_t)(dc0 + dd) * DD + e];
        const float4* q4 = (const float4*)&s_qc[dd * 32];
#pragma unroll
        for (int j = 0; j < 8; j++) {
            float4 q = q4[j];
            acc[4 * j + 0] += q.x * v;
            acc[4 * j + 1] += q.y * v;
            acc[4 * j + 2] += q.z * v;
            acc[4 * j + 3] += q.w * v;
        }
    }
#pragma unroll
    for (int b = 0; b < 32; b++)
        g_upart[blockIdx.y][b * DD + e] = acc[b];
}

__global__ void k_sumu() {
    int idx = blockIdx.x * 256 + threadIdx.x;
    float s = 0.f;
#pragma unroll
    for (int z = 0; z < 16; z++) s += g_upart[z][idx];
    g_u[idx] = s;
}

// ---------------- Kernel 6: centers C + partial scores ---------------------
// grid (256 slots, B, 4 d-quarters), 256 threads; members prefetched, MLP=4.
__global__ void k_centers(const float* __restrict__ tok2d) {
    __shared__ int s_m[NPIX];
    const int s = blockIdx.x, b = blockIdx.y, z = blockIdx.z;
    const int t = threadIdx.x;
    const int d = z * 256 + t;
    const int start = g_start[b * KS + s];
    const float cf = g_cntf[b * KS + s];
    const int cnt = (int)cf;
    for (int l = t; l < cnt; l += 256) s_m[l] = g_mem[b * NPIX + start + l];
    __syncthreads();
    float a0 = 0.f, a1 = 0.f, a2 = 0.f, a3 = 0.f;
    int m = 0;
    for (; m + 4 <= cnt; m += 4) {
        a0 += tok2d[((size_t)(b * NT + 1 + s_m[m + 0])) * DD + d];
        a1 += tok2d[((size_t)(b * NT + 1 + s_m[m + 1])) * DD + d];
        a2 += tok2d[((size_t)(b * NT + 1 + s_m[m + 2])) * DD + d];
        a3 += tok2d[((size_t)(b * NT + 1 + s_m[m + 3])) * DD + d];
    }
    for (; m < cnt; m++) a0 += tok2d[((size_t)(b * NT + 1 + s_m[m])) * DD + d];
    float acc = (a0 + a1) + (a2 + a3);
    const float c = acc / fmaxf(cf, 1.f);
    g_C[((size_t)b * KS + s) * DD + d] = c;
    float part = c * g_u[b * DD + d];
    __shared__ float red[8];
    for (int off = 16; off; off >>= 1) part += __shfl_xor_sync(0xffffffffu, part, off);
    if ((t & 31) == 0) red[t >> 5] = part;
    __syncthreads();
    if (t < 8) {
        float v = red[t];
        for (int off = 4; off; off >>= 1) v += __shfl_xor_sync(0xffu, v, off);
        if (t == 0) g_spart[(b * KS + s) * 4 + z] = v;
    }
}

// ---------------- Kernel 7: top-128 of scores (ties -> lower index) --------
__global__ void k_top() {
    __shared__ float ss[KS];
    __shared__ int fl[KS];
    const int t = threadIdx.x, b = blockIdx.x;
    const float cf = g_cntf[b * KS + t];
    float sc = 0.f;
#pragma unroll
    for (int z = 0; z < 4; z++) sc += g_spart[(b * KS + t) * 4 + z];
    ss[t] = (cf > 0.f) ? sc : -INFINITY;
    __syncthreads();
    const float sv = ss[t];
    int rank = 0;
    for (int k = 0; k < KS; k++) {
        float o = ss[k];
        rank += (o > sv) || (o == sv && k < t);
    }
    fl[t] = (rank < MT);
    __syncthreads();
    if (fl[t]) {
        int pos = 0;
        for (int k = 0; k < t; k++) pos += fl[k];
        g_sel[b * MT + pos] = t;
    }
}

// ---------------- Kernel 8: gather output ----------------------------------
__global__ void k_gather(float* __restrict__ out) {
    const int tt = blockIdx.x, b = blockIdx.y, t = threadIdx.x;
    const int k = g_sel[b * MT + tt];
    const float4* src = (const float4*)(g_C + ((size_t)b * KS + k) * DD);
    float4* dst = (float4*)(out + ((size_t)b * MT + tt) * DD);
    dst[t] = src[t];
}

// ---------------------------------------------------------------------------
extern "C" void kernel_launch(void* const* d_in, const int* in_sizes, int n_in,
                              void* d_out, int out_size) {
    (void)in_sizes; (void)n_in; (void)out_size;
    const float* tok2d = (const float*)d_in[0];
    const float* dw_w  = (const float*)d_in[1];
    const float* pw_w  = (const float*)d_in[2];
    const float* pw_b  = (const float*)d_in[3];
    const float* q_w   = (const float*)d_in[4];
    const float* q_b   = (const float*)d_in[5];
    const float* v_w   = (const float*)d_in[6];
    float* out = (float*)d_out;

    k_affdw   <<<dim3(6, BB, 4), 384>>>(tok2d, dw_w, pw_w);
    k_parent  <<<BB * NPIX / 128, 128>>>(pw_b);
    k_cluster <<<BB, NPIX>>>();
    k_qcls    <<<dim3(128, 4), 256>>>(tok2d, q_w);
    k_u       <<<dim3(8, 16), 128>>>(v_w, q_b);
    k_sumu    <<<BB * DD / 256, 256>>>();
    k_centers <<<dim3(KS, BB, 4), 256>>>(tok2d);
    k_top     <<<BB, 256>>>();
    k_gather  <<<dim3(MT, BB), 256>>>(out);
}

// round 3
// speedup vs baseline: 1.4408x; 1.2877x over previous
#include <cuda_runtime.h>
#include <math.h>

#define HH 24
#define WW 24
#define NPIX 576
#define DD 1024
#define BB 32
#define KS 256
#define MT 128
#define NT 577

// ---------------- scratch (device globals; no allocation allowed) ----------
__device__ float g_affp[4][BB * NPIX * 9];          // partial 9-logits per d-quarter
__device__ float g_cntf[BB * KS];                   // per-slot counts (float)
__device__ int   g_start[BB * KS];                  // member-list offsets
__device__ int   g_mem[BB * NPIX];                  // member lists (grouped by slot)
__device__ float g_C[(size_t)BB * KS * DD];         // cluster centers (33.5 MB)
__device__ float g_qpart[8][BB * DD];               // partial Q_cls (per e-chunk)
__device__ float g_upart[32][BB * DD];              // partial u (per d-chunk)
__device__ float g_u[BB * DD];                      // u = Q_cls @ v_w
__device__ float g_score[BB * KS];                  // scores
__device__ int   g_sel[BB * MT];                    // final top-128 slot ids

// ---------------- Kernel 1: FUSED depthwise 3x3 + pointwise (D->9) --------
__global__ void __launch_bounds__(384) k_affdw(const float* __restrict__ tok2d,
                        const float* __restrict__ dww,
                        const float* __restrict__ pww) {
    __shared__ float s_tile[32 * 157];
    __shared__ float s_dww[256 * 9];
    __shared__ float s_pw[9 * 256];
    const int t  = threadIdx.x;
    const int h0 = blockIdx.x * 4;
    const int b  = blockIdx.y;
    const int z  = blockIdx.z;

    for (int l = t; l < 256 * 9; l += 384) s_dww[l] = dww[z * 256 * 9 + l];
    for (int l = t; l < 9 * 256; l += 384) {
        int o = l >> 8, dq = l & 255;
        s_pw[l] = pww[o * DD + z * 256 + dq];
    }

    const int quad = t >> 4;
    const int j    = t & 15;
    const int qr   = quad / 6;
    const int qw   = (quad % 6) * 4;

    float acc[36];
#pragma unroll
    for (int i = 0; i < 36; i++) acc[i] = 0.f;

    for (int ch = 0; ch < 8; ch++) {
        __syncthreads();
        for (int l = t; l < 32 * 156; l += 384) {
            int dl = l & 31, pos = l >> 5;
            int c = pos % 26, r = pos / 26;
            int gh = h0 + r - 1, gw = c - 1;
            float v = 0.f;
            if (gh >= 0 && gh < HH && gw >= 0 && gw < WW)
                v = tok2d[((size_t)(b * NT + 1 + gh * WW + gw)) * DD + z * 256 + ch * 32 + dl];
            s_tile[dl * 157 + pos] = v;
        }
        __syncthreads();
#pragma unroll
        for (int i = 0; i < 2; i++) {
            const int dl = i * 16 + j;
            const int dq = ch * 32 + dl;
            float wd[9], wp[9];
#pragma unroll
            for (int k = 0; k < 9; k++) wd[k] = s_dww[dq * 9 + k];
#pragma unroll
            for (int o = 0; o < 9; o++) wp[o] = s_pw[o * 256 + dq];
            float tv[3][6];
#pragma unroll
            for (int kh = 0; kh < 3; kh++)
#pragma unroll
                for (int c6 = 0; c6 < 6; c6++)
                    tv[kh][c6] = s_tile[dl * 157 + (qr + kh) * 26 + qw + c6];
#pragma unroll
            for (int px = 0; px < 4; px++) {
                float dwv = 0.f;
#pragma unroll
                for (int kh = 0; kh < 3; kh++)
#pragma unroll
                    for (int kw = 0; kw < 3; kw++)
                        dwv += tv[kh][px + kw] * wd[kh * 3 + kw];
#pragma unroll
                for (int o = 0; o < 9; o++) acc[px * 9 + o] += dwv * wp[o];
            }
        }
    }
#pragma unroll
    for (int i = 0; i < 36; i++)
#pragma unroll
        for (int off = 8; off; off >>= 1)
            acc[i] += __shfl_xor_sync(0xffffffffu, acc[i], off);

    if (j == 0) {
#pragma unroll
        for (int px = 0; px < 4; px++) {
            int n = (h0 + qr) * WW + qw + px;
            float* dst = &g_affp[z][(b * NPIX + n) * 9];
#pragma unroll
            for (int o = 0; o < 9; o++) dst[o] = acc[px * 9 + o];
        }
    }
}

// ---------------- Kernel 2: parent (inline) + pointer jumping + clusters ---
__global__ void k_cluster(const float* __restrict__ pwb) {
    __shared__ int s_par[NPIX], s_cnt[NPIX], s_hist[NPIX + 1];
    __shared__ int s_flag[NPIX], s_slotof[NPIX], s_startsh[KS];
    __shared__ int s_cstar, s_take;
    const int i = threadIdx.x;
    const int b = blockIdx.x;

    // --- compute own parent from logit partials ---
    {
        float l9[9];
#pragma unroll
        for (int o = 0; o < 9; o++) l9[o] = pwb[o];
#pragma unroll
        for (int z = 0; z < 4; z++) {
            const float* src = &g_affp[z][(b * NPIX + i) * 9];
#pragma unroll
            for (int o = 0; o < 9; o++) l9[o] += src[o];
        }
        float mx = -1e30f;
#pragma unroll
        for (int o = 0; o < 9; o++) mx = fmaxf(mx, l9[o]);
        float e[9];
#pragma unroll
        for (int o = 0; o < 9; o++) e[o] = expf(l9[o] - mx);
        const int h = i / WW, w = i - (i / WW) * WW;
        float cs[9]; int cid[9]; int m = 0;
        for (int k = 0; k < 9; k++) {
            int dy = k / 3 - 1, dx = k % 3 - 1;
            int ny = min(max(h + dy, 0), HH - 1);
            int nx = min(max(w + dx, 0), WW - 1);
            int col = ny * WW + nx;
            int found = -1;
            for (int jj = 0; jj < m; jj++) if (cid[jj] == col) { found = jj; break; }
            if (found >= 0) cs[found] += e[k];
            else { cid[m] = col; cs[m] = e[k]; m++; }
        }
        int best = cid[0]; float bs = cs[0];
        for (int jj = 1; jj < m; jj++)
            if (cs[jj] > bs || (cs[jj] == bs && cid[jj] < best)) { bs = cs[jj]; best = cid[jj]; }
        s_par[i] = best;
    }
    __syncthreads();
    for (int it = 0; it < 6; it++) {
        int v = s_par[s_par[i]];
        __syncthreads();
        s_par[i] = v;
        __syncthreads();
    }
    s_cnt[i] = 0; s_hist[i] = 0;
    if (i == 0) s_hist[NPIX] = 0;
    __syncthreads();
    atomicAdd(&s_cnt[s_par[i]], 1);
    __syncthreads();
    atomicAdd(&s_hist[s_cnt[i]], 1);
    __syncthreads();
    {
        int nrep = (i == 0) ? 2 : 1;
        for (int rep = 0; rep < nrep; rep++) {
            int v = (rep == 0) ? i : NPIX;
            int gt = 0;
            for (int vv = v + 1; vv <= NPIX; vv++) gt += s_hist[vv];
            if (gt < KS && gt + s_hist[v] >= KS) { s_cstar = v; s_take = KS - gt; }
        }
    }
    __syncthreads();
    const int cstar = s_cstar, take = s_take;
    const int ci = s_cnt[i];
    int eqb = 0;
    for (int j = 0; j < i; j++) eqb += (s_cnt[j] == cstar);
    const int fl = (ci > cstar) || (ci == cstar && eqb < take);
    s_flag[i] = fl;
    __syncthreads();
    int slot = 0, start = 0;
    for (int j = 0; j < i; j++) {
        int f = s_flag[j];
        slot += f;
        start += f ? s_cnt[j] : 0;
    }
    s_slotof[i] = fl ? slot : -1;
    if (fl) {
        g_cntf[b * KS + slot]  = (float)ci;
        g_start[b * KS + slot] = start;
        s_startsh[slot] = start;
    }
    __syncthreads();
    const int r = s_par[i];
    const int sl = s_slotof[r];
    if (sl >= 0) {
        int pos = 0;
        for (int j = 0; j < i; j++) pos += (s_slotof[s_par[j]] == sl);
        g_mem[b * NPIX + s_startsh[sl] + pos] = i;
    }
}

// ---------------- Kernel 4: Q_cls partials, 8 e-chunks of 128 --------------
__global__ void k_qcls(const float* __restrict__ tok2d,
                       const float* __restrict__ qw) {
    __shared__ float s_cls[32 * 128];
    const int t = threadIdx.x, lane = t & 31, warp = t >> 5;
    const int d = blockIdx.x * 8 + warp;
    const int ec = blockIdx.y;
    for (int l = t; l < 32 * 128; l += 256) {
        int b = l >> 7, e = l & 127;
        s_cls[l] = tok2d[(size_t)b * NT * DD + ec * 128 + e];
    }
    __syncthreads();
    float acc[32];
#pragma unroll
    for (int b = 0; b < 32; b++) acc[b] = 0.f;
#pragma unroll
    for (int ii = 0; ii < 4; ii++) {
        int el = lane + 32 * ii;
        float wv = qw[(size_t)d * DD + ec * 128 + el];
#pragma unroll
        for (int b = 0; b < 32; b++) acc[b] += wv * s_cls[b * 128 + el];
    }
    for (int b = 0; b < 32; b++) {
        float v = acc[b];
        for (int off = 16; off; off >>= 1) v += __shfl_xor_sync(0xffffffffu, v, off);
        if (lane == 0) g_qpart[ec][b * DD + d] = v;
    }
}

// ---------------- Kernel 5: u partials = Qc @ v_w, 32 d-chunks of 32 -------
__global__ void k_u(const float* __restrict__ vw,
                    const float* __restrict__ qb) {
    __shared__ float s_qc[32 * 32];  // [d][b]
    const int t = threadIdx.x;
    const int e = blockIdx.x * 128 + t;
    const int dc0 = blockIdx.y * 32;
    for (int l = t; l < 32 * 32; l += 128) {
        int d = l >> 5, b = l & 31;
        float v = qb[dc0 + d];
#pragma unroll
        for (int z = 0; z < 8; z++) v += g_qpart[z][b * DD + dc0 + d];
        s_qc[l] = v;
    }
    __syncthreads();
    float acc[32];
#pragma unroll
    for (int b = 0; b < 32; b++) acc[b] = 0.f;
#pragma unroll
    for (int dd = 0; dd < 32; dd++) {
        float v = vw[(size_t)(dc0 + dd) * DD + e];
        const float4* q4 = (const float4*)&s_qc[dd * 32];
#pragma unroll
        for (int j = 0; j < 8; j++) {
            float4 q = q4[j];
            acc[4 * j + 0] += q.x * v;
            acc[4 * j + 1] += q.y * v;
            acc[4 * j + 2] += q.z * v;
            acc[4 * j + 3] += q.w * v;
        }
    }
#pragma unroll
    for (int b = 0; b < 32; b++)
        g_upart[blockIdx.y][b * DD + e] = acc[b];
}

__global__ void k_sumu() {
    int idx = blockIdx.x * 256 + threadIdx.x;
    float s = 0.f;
#pragma unroll
    for (int z = 0; z < 32; z++) s += g_upart[z][idx];
    g_u[idx] = s;
}

// ---------------- Kernel 6: centers (full row per block) + score -----------
// grid (KS, B), 256 threads; thread owns 4 d via float4; MLP=4 accumulators.
__global__ void k_centers(const float* __restrict__ tok2d) {
    __shared__ int s_m[NPIX];
    __shared__ float red[8];
    const int s = blockIdx.x, b = blockIdx.y;
    const int t = threadIdx.x;
    const int start = g_start[b * KS + s];
    const float cf = g_cntf[b * KS + s];
    const int cnt = (int)cf;
    for (int l = t; l < cnt; l += 256) s_m[l] = g_mem[b * NPIX + start + l];
    __syncthreads();
    const float4* base = (const float4*)tok2d;
    float4 a0 = {0.f,0.f,0.f,0.f}, a1 = a0, a2 = a0, a3 = a0;
    int m = 0;
    for (; m + 4 <= cnt; m += 4) {
        float4 v0 = base[(size_t)(b * NT + 1 + s_m[m + 0]) * 256 + t];
        float4 v1 = base[(size_t)(b * NT + 1 + s_m[m + 1]) * 256 + t];
        float4 v2 = base[(size_t)(b * NT + 1 + s_m[m + 2]) * 256 + t];
        float4 v3 = base[(size_t)(b * NT + 1 + s_m[m + 3]) * 256 + t];
        a0.x += v0.x; a0.y += v0.y; a0.z += v0.z; a0.w += v0.w;
        a1.x += v1.x; a1.y += v1.y; a1.z += v1.z; a1.w += v1.w;
        a2.x += v2.x; a2.y += v2.y; a2.z += v2.z; a2.w += v2.w;
        a3.x += v3.x; a3.y += v3.y; a3.z += v3.z; a3.w += v3.w;
    }
    for (; m < cnt; m++) {
        float4 v0 = base[(size_t)(b * NT + 1 + s_m[m]) * 256 + t];
        a0.x += v0.x; a0.y += v0.y; a0.z += v0.z; a0.w += v0.w;
    }
    float4 acc;
    acc.x = (a0.x + a1.x) + (a2.x + a3.x);
    acc.y = (a0.y + a1.y) + (a2.y + a3.y);
    acc.z = (a0.z + a1.z) + (a2.z + a3.z);
    acc.w = (a0.w + a1.w) + (a2.w + a3.w);
    const float dv = fmaxf(cf, 1.f);
    float4 c;
    c.x = acc.x / dv; c.y = acc.y / dv; c.z = acc.z / dv; c.w = acc.w / dv;
    ((float4*)g_C)[((size_t)b * KS + s) * 256 + t] = c;
    float4 u4 = ((const float4*)g_u)[b * 256 + t];
    float part = c.x * u4.x + c.y * u4.y + c.z * u4.z + c.w * u4.w;
    for (int off = 16; off; off >>= 1) part += __shfl_xor_sync(0xffffffffu, part, off);
    if ((t & 31) == 0) red[t >> 5] = part;
    __syncthreads();
    if (t < 8) {
        float v = red[t];
        for (int off = 4; off; off >>= 1) v += __shfl_xor_sync(0xffu, v, off);
        if (t == 0) g_score[b * KS + s] = v;
    }
}

// ---------------- Kernel 7: top-128 of scores (ties -> lower index) --------
__global__ void k_top() {
    __shared__ float ss[KS];
    __shared__ int fl[KS];
    const int t = threadIdx.x, b = blockIdx.x;
    const float cf = g_cntf[b * KS + t];
    ss[t] = (cf > 0.f) ? g_score[b * KS + t] : -INFINITY;
    __syncthreads();
    const float sv = ss[t];
    int rank = 0;
    for (int k = 0; k < KS; k++) {
        float o = ss[k];
        rank += (o > sv) || (o == sv && k < t);
    }
    fl[t] = (rank < MT);
    __syncthreads();
    if (fl[t]) {
        int pos = 0;
        for (int k = 0; k < t; k++) pos += fl[k];
        g_sel[b * MT + pos] = t;
    }
}

// ---------------- Kernel 8: gather output ----------------------------------
__global__ void k_gather(float* __restrict__ out) {
    const int tt = blockIdx.x, b = blockIdx.y, t = threadIdx.x;
    const int k = g_sel[b * MT + tt];
    const float4* src = (const float4*)(g_C + ((size_t)b * KS + k) * DD);
    float4* dst = (float4*)(out + ((size_t)b * MT + tt) * DD);
    dst[t] = src[t];
}

// ---------------------------------------------------------------------------
extern "C" void kernel_launch(void* const* d_in, const int* in_sizes, int n_in,
                              void* d_out, int out_size) {
    (void)in_sizes; (void)n_in; (void)out_size;
    const float* tok2d = (const float*)d_in[0];
    const float* dw_w  = (const float*)d_in[1];
    const float* pw_w  = (const float*)d_in[2];
    const float* pw_b  = (const float*)d_in[3];
    const float* q_w   = (const float*)d_in[4];
    const float* q_b   = (const float*)d_in[5];
    const float* v_w   = (const float*)d_in[6];
    float* out = (float*)d_out;

    k_affdw   <<<dim3(6, BB, 4), 384>>>(tok2d, dw_w, pw_w);
    k_cluster <<<BB, NPIX>>>(pw_b);
    k_qcls    <<<dim3(128, 8), 256>>>(tok2d, q_w);
    k_u       <<<dim3(8, 32), 128>>>(v_w, q_b);
    k_sumu    <<<BB * DD / 256, 256>>>();
    k_centers <<<dim3(KS, BB), 256>>>(tok2d);
    k_top     <<<BB, 256>>>();
    k_gather  <<<dim3(MT, BB), 256>>>(out);
}